// round 15
// baseline (speedup 1.0000x reference)
#include <cuda_runtime.h>

#define DD 512
#define BB 128
#define EPSF 1e-5f
#define LOG2E_F 1.4426950408889634f
#define TJ 32
#define MATSZ (384 * 512)
#define NR 384

// scratch (static device memory — no allocations)
__device__ float g_y  [3 * BB * DD];
__device__ float g_wt [3 * DD * DD];      // k-major weights: [mat][k][m]
__device__ float g_st [2 * DD * NR];      // k-major sources: [mat][k][row] (H, KQ)
__device__ float g_yT [DD * NR];          // k-major y: [k][row]
__device__ float g_part[16 * MATSZ];      // K-split partials

struct Ptr3 { const float* p[3]; };

__device__ __forceinline__ float ex2f(float x) {
    float y;
    asm("ex2.approx.ftz.f32 %0, %1;" : "=f"(y) : "f"(x));
    return y;
}

// ===================== transpose weights: g_wt[z][d][m] = W_z[m][d] =====================
__global__ void __launch_bounds__(256)
k_transpose(const float* __restrict__ W0, const float* __restrict__ W1,
            const float* __restrict__ W2)
{
    __shared__ float t[32][33];
    const float* W = (blockIdx.z == 0) ? W0 : (blockIdx.z == 1) ? W1 : W2;
    float* O = g_wt + (size_t)blockIdx.z * DD * DD;
    int x  = blockIdx.x * 32 + threadIdx.x;
    int y0 = blockIdx.y * 32;
    #pragma unroll
    for (int i = threadIdx.y; i < 32; i += 8)
        t[i][threadIdx.x] = W[(size_t)(y0 + i) * DD + x];
    __syncthreads();
    int xo  = blockIdx.y * 32 + threadIdx.x;
    int yo0 = blockIdx.x * 32;
    #pragma unroll
    for (int i = threadIdx.y; i < 32; i += 8)
        O[(size_t)(yo0 + i) * DD + xo] = t[threadIdx.x][i];
}

// ===================== transpose sources: g_st[z][k][row] = src_z[row][k] =====================
__global__ void __launch_bounds__(256)
k_transpose2(Ptr3 A, Ptr3 B)
{
    __shared__ float tl[32][33];
    int z = blockIdx.z;
    Ptr3 S = z ? B : A;
    float* dst = g_st + (size_t)z * DD * NR;
    int col0 = blockIdx.x * 32;     // feature (k) dim
    int row0 = blockIdx.y * 32;     // row dim
    int tx = threadIdx.x;
    #pragma unroll
    for (int i = threadIdx.y; i < 32; i += 8) {
        int row = row0 + i;
        const float* p = S.p[row >> 7];
        tl[i][tx] = p[(size_t)(row & 127) * DD + col0 + tx];
    }
    __syncthreads();
    #pragma unroll
    for (int i = threadIdx.y; i < 32; i += 8)
        dst[(size_t)(col0 + i) * NR + row0 + tx] = tl[tx][i];
}

// ===================== GEMM vS2: both tiles k-major, smem-only compute =====================
// g_part[z][row][col] = sum_{k in slice} srcT[k][row] * Wt[k][col]
// block 128 thr; tile 32r x 64c, K=64; thread tile 4r x 4c; inner: 2 LDS.128 + 16 FMA.
// grid: (12 rowtiles, 8 coltiles, nmat * NKS)
struct GS {
    const float* srcT[2];   // k-major [512][384]
    int wtsel[2];
};

template <int NKS>
__global__ void __launch_bounds__(128)
k_gemmS2(GS a)
{
    __shared__ __align__(16) float sS[64][36];   // [k][row]  9.2 KB
    __shared__ __align__(16) float sW[64][68];   // [k][col] 17.4 KB

    int tid = threadIdx.x;
    int rt = blockIdx.x, ct = blockIdx.y, z = blockIdx.z;
    int mat = z / NKS, ks = z % NKS;
    int r0 = rt * 32, c0 = ct * 64, k0 = ks * 64;

    const float* srcT = a.srcT[mat] + (size_t)k0 * NR + r0;
    const float* wt   = g_wt + (size_t)a.wtsel[mat] * DD * DD + (size_t)k0 * DD + c0;

    // stage sS: 64 k x 32 rows (straight coalesced copy)
    #pragma unroll
    for (int it = 0; it < 4; it++) {
        int idx = it * 128 + tid;
        int k = idx >> 3, r4 = idx & 7;
        *(float4*)&sS[k][r4 * 4] = *(const float4*)(srcT + (size_t)k * NR + r4 * 4);
    }
    // stage sW: 64 k x 64 cols (straight coalesced copy)
    #pragma unroll
    for (int it = 0; it < 8; it++) {
        int idx = it * 128 + tid;
        int k = idx >> 4, q = idx & 15;
        *(float4*)&sW[k][q * 4] = *(const float4*)(wt + (size_t)k * DD + q * 4);
    }
    __syncthreads();

    int c4 = tid & 15;     // 16 col-quads -> 64 cols
    int rg = tid >> 4;     // 8 row-quads -> 32 rows

    float4 acc[4];
    #pragma unroll
    for (int r = 0; r < 4; r++) acc[r] = make_float4(0.f, 0.f, 0.f, 0.f);

    #pragma unroll 8
    for (int k = 0; k < 64; k++) {
        float4 av = *(const float4*)&sS[k][rg * 4];    // 4 rows (broadcast)
        float4 wv = *(const float4*)&sW[k][c4 * 4];    // 4 cols
        acc[0].x = fmaf(av.x, wv.x, acc[0].x);
        acc[0].y = fmaf(av.x, wv.y, acc[0].y);
        acc[0].z = fmaf(av.x, wv.z, acc[0].z);
        acc[0].w = fmaf(av.x, wv.w, acc[0].w);
        acc[1].x = fmaf(av.y, wv.x, acc[1].x);
        acc[1].y = fmaf(av.y, wv.y, acc[1].y);
        acc[1].z = fmaf(av.y, wv.z, acc[1].z);
        acc[1].w = fmaf(av.y, wv.w, acc[1].w);
        acc[2].x = fmaf(av.z, wv.x, acc[2].x);
        acc[2].y = fmaf(av.z, wv.y, acc[2].y);
        acc[2].z = fmaf(av.z, wv.z, acc[2].z);
        acc[2].w = fmaf(av.z, wv.w, acc[2].w);
        acc[3].x = fmaf(av.w, wv.x, acc[3].x);
        acc[3].y = fmaf(av.w, wv.y, acc[3].y);
        acc[3].z = fmaf(av.w, wv.z, acc[3].z);
        acc[3].w = fmaf(av.w, wv.w, acc[3].w);
    }

    float* outp = g_part + (size_t)z * MATSZ;
    #pragma unroll
    for (int r = 0; r < 4; r++) {
        int row = r0 + 4 * rg + r;
        *(float4*)(outp + (size_t)row * DD + c0 + c4 * 4) = acc[r];
    }
}

// ===================== fc final reduce: out = p0..p7 + fc_b + y (float4) =====================
__global__ void __launch_bounds__(256)
k_reduce2(const float* __restrict__ fcb, float* __restrict__ out)
{
    int idx = blockIdx.x * 256 + threadIdx.x;        // float4 index
    size_t i = (size_t)idx * 4;
    int col = (idx & 127) * 4;
    float4 s = *(const float4*)(g_part + i);
    #pragma unroll
    for (int q = 1; q < 8; q++) {
        float4 v = *(const float4*)(g_part + (size_t)q * MATSZ + i);
        s.x += v.x; s.y += v.y; s.z += v.z; s.w += v.w;
    }
    float4 bb = *(const float4*)(fcb + col);
    float4 yy = *(const float4*)(g_y + i);
    s.x += bb.x + yy.x;
    s.y += bb.y + yy.y;
    s.z += bb.z + yy.z;
    s.w += bb.w + yy.w;
    *(float4*)(out + i) = s;
}

// ---- block reductions over 512 threads (16 warps) ----
__device__ __forceinline__ float blockReduceSum(float v, float* red) {
    int tid = threadIdx.x, lane = tid & 31, wid = tid >> 5;
    #pragma unroll
    for (int o = 16; o > 0; o >>= 1) v += __shfl_down_sync(0xffffffffu, v, o);
    if (lane == 0) red[wid] = v;
    __syncthreads();
    if (wid == 0) {
        float x = (lane < 16) ? red[lane] : 0.0f;
        #pragma unroll
        for (int o = 8; o > 0; o >>= 1) x += __shfl_down_sync(0xffffffffu, x, o);
        if (lane == 0) red[0] = x;
    }
    __syncthreads();
    float r = red[0];
    __syncthreads();
    return r;
}

__device__ __forceinline__ float blockReduceMax(float v, float* red) {
    int tid = threadIdx.x, lane = tid & 31, wid = tid >> 5;
    #pragma unroll
    for (int o = 16; o > 0; o >>= 1) v = fmaxf(v, __shfl_down_sync(0xffffffffu, v, o));
    if (lane == 0) red[wid] = v;
    __syncthreads();
    if (wid == 0) {
        float x = (lane < 16) ? red[lane] : -3.4e38f;
        #pragma unroll
        for (int o = 8; o > 0; o >>= 1) x = fmaxf(x, __shfl_down_sync(0xffffffffu, x, o));
        if (lane == 0) red[0] = x;
    }
    __syncthreads();
    float r = red[0];
    __syncthreads();
    return r;
}

__device__ __forceinline__ float blockReduceMin(float v, float* red) {
    int tid = threadIdx.x, lane = tid & 31, wid = tid >> 5;
    #pragma unroll
    for (int o = 16; o > 0; o >>= 1) v = fminf(v, __shfl_down_sync(0xffffffffu, v, o));
    if (lane == 0) red[wid] = v;
    __syncthreads();
    if (wid == 0) {
        float x = (lane < 16) ? red[lane] : 3.4e38f;
        #pragma unroll
        for (int o = 8; o > 0; o >>= 1) x = fminf(x, __shfl_down_sync(0xffffffffu, x, o));
        if (lane == 0) red[0] = x;
    }
    __syncthreads();
    float r = red[0];
    __syncthreads();
    return r;
}

// ---- main fused kernel: one block per (batch, channel) ----
// Folds the stage-1 K-split-8 reduction + bias into its loads; also emits k-major y.
__global__ void __launch_bounds__(512)
k_main(Ptr3 x, Ptr3 h, Ptr3 kq,
       const float* __restrict__ bk, const float* __restrict__ bq,
       const float* __restrict__ kn_g, const float* __restrict__ kn_b,
       const float* __restrict__ norm_g, const float* __restrict__ norm_b)
{
    extern __shared__ float E[];              // [512][TJ+1]
    __shared__ float s_s[DD], s_u2[DD], s_v[DD];
    __shared__ float Zpart[16][TJ + 1];
    __shared__ float coefT[TJ];
    __shared__ float red[32];

    const int ESTR = TJ + 1;

    int b = blockIdx.x, c = blockIdx.y, tid = threadIdx.x;
    int row = c * BB + b;
    size_t ri = (size_t)row * DD + tid;

    float wk = bk[tid];
    float wq = bq[tid];
    #pragma unroll
    for (int q = 0; q < 8; q++) wk += g_part[(size_t)q * MATSZ + ri];
    #pragma unroll
    for (int q = 8; q < 16; q++) wq += g_part[(size_t)q * MATSZ + ri];

    float kv = h.p[c][(size_t)b * DD + tid];
    float qv = kq.p[c][(size_t)b * DD + tid];
    float vv = x.p[c][(size_t)b * DD + tid];

    const float inv_d = 1.0f / (float)DD;
    float mu_wk  = blockReduceSum(wk, red) * inv_d;
    float dk     = wk - mu_wk;
    float var_wk = blockReduceSum(dk * dk, red) * inv_d;
    float mu_wq  = blockReduceSum(wq, red) * inv_d;
    float dq     = wq - mu_wq;
    float var_wq = blockReduceSum(dq * dq, red) * inv_d;

    float gg = kn_g[tid];
    float cb = kn_b[tid];

    float si = kv * rsqrtf(kv * kv * var_wk + EPSF);
    float ti = qv * rsqrtf(qv * qv * var_wq + EPSF);
    float Ai = dk * gg;
    float Bi = dq * gg;

    float P    = blockReduceSum(Ai * ti, red);
    float Qs   = blockReduceSum(Ai, red);
    float smax = blockReduceMax(si, red);
    float smin = blockReduceMin(si, red);

    float u2 = (P * Bi + Qs * cb) * LOG2E_F;
    s_s[tid]  = si;
    s_u2[tid] = u2;
    s_v[tid]  = vv;
    __syncthreads();

    int g = tid >> 5;
    int j = tid & 31;

    float acc = 0.0f;

    #pragma unroll 1
    for (int jt = 0; jt < DD; jt += TJ) {
        float u2j = s_u2[jt + j];
        float m2j = fmaxf(u2j * smax, u2j * smin);
        float Zl = 0.0f;

        float* Ecol = E + (size_t)(g * 32) * ESTR + j;
        const float* sbase = s_s + g * 32;
        #pragma unroll
        for (int i4 = 0; i4 < 32; i4 += 4) {
            float4 s4 = *(const float4*)(sbase + i4);
            float e0 = ex2f(fmaf(s4.x, u2j, -m2j));
            float e1 = ex2f(fmaf(s4.y, u2j, -m2j));
            float e2 = ex2f(fmaf(s4.z, u2j, -m2j));
            float e3 = ex2f(fmaf(s4.w, u2j, -m2j));
            Zl += (e0 + e1) + (e2 + e3);
            Ecol[(i4 + 0) * ESTR] = e0;
            Ecol[(i4 + 1) * ESTR] = e1;
            Ecol[(i4 + 2) * ESTR] = e2;
            Ecol[(i4 + 3) * ESTR] = e3;
        }
        Zpart[g][j] = Zl;
        __syncthreads();

        if (tid < TJ) {
            float zt = 0.0f;
            #pragma unroll
            for (int w = 0; w < 16; w++) zt += Zpart[w][tid];
            coefT[tid] = s_v[jt + tid] / zt;
        }
        __syncthreads();

        const float* Erow = E + (size_t)tid * ESTR;
        #pragma unroll
        for (int jj = 0; jj < TJ; jj += 4) {
            float c0 = coefT[jj + 0], c1 = coefT[jj + 1];
            float c2 = coefT[jj + 2], c3 = coefT[jj + 3];
            acc = fmaf(c0, Erow[jj + 0], acc);
            acc = fmaf(c1, Erow[jj + 1], acc);
            acc = fmaf(c2, Erow[jj + 2], acc);
            acc = fmaf(c3, Erow[jj + 3], acc);
        }
        __syncthreads();
    }

    float y     = acc + vv;
    float mu_y  = blockReduceSum(y, red) * inv_d;
    float dy    = y - mu_y;
    float var_y = blockReduceSum(dy * dy, red) * inv_d;
    float yn    = dy * rsqrtf(var_y + EPSF) * norm_g[tid] + norm_b[tid];

    g_y [(size_t)row * DD + tid] = yn;
    g_yT[(size_t)tid * NR + row] = yn;     // k-major copy for fc staging
}

extern "C" void kernel_launch(void* const* d_in, const int* in_sizes, int n_in,
                              void* d_out, int out_size)
{
    (void)in_sizes; (void)n_in; (void)out_size;
    const float* r    = (const float*)d_in[0];
    const float* g    = (const float*)d_in[1];
    const float* b    = (const float*)d_in[2];
    const float* h_r  = (const float*)d_in[3];
    const float* h_g  = (const float*)d_in[4];
    const float* h_b  = (const float*)d_in[5];
    const float* k_r  = (const float*)d_in[6];
    const float* k_g  = (const float*)d_in[7];
    const float* k_b  = (const float*)d_in[8];
    const float* Wk   = (const float*)d_in[9];
    const float* bk   = (const float*)d_in[10];
    const float* Wq   = (const float*)d_in[11];
    const float* bq   = (const float*)d_in[12];
    const float* kn_g = (const float*)d_in[13];
    const float* kn_b = (const float*)d_in[14];
    const float* norm_g = (const float*)d_in[15];
    const float* norm_b = (const float*)d_in[16];
    const float* fc_w = (const float*)d_in[17];
    const float* fc_b = (const float*)d_in[18];
    float* out = (float*)d_out;

    Ptr3 X  = {{ r,   g,   b   }};
    Ptr3 H  = {{ h_r, h_g, h_b }};
    Ptr3 KQ = {{ k_r, k_g, k_b }};

    const size_t E_BYTES = (size_t)DD * (TJ + 1) * sizeof(float);

    static float* st_dev = nullptr;
    static float* yT_dev = nullptr;
    if (st_dev == nullptr) {
        void* p = nullptr;
        cudaGetSymbolAddress(&p, g_st); st_dev = (float*)p;
        cudaGetSymbolAddress(&p, g_yT); yT_dev = (float*)p;
        cudaFuncSetAttribute(k_main, cudaFuncAttributeMaxDynamicSharedMemorySize,
                             (int)E_BYTES);
    }

    // Stage 0a: transpose weights -> g_wt (k-major)
    k_transpose<<<dim3(16, 16, 3), dim3(32, 8)>>>(Wk, Wq, fc_w);
    // Stage 0b: transpose sources -> g_st (k-major)
    k_transpose2<<<dim3(16, 12, 2), dim3(32, 8)>>>(H, KQ);

    // Stage 1: w_k / w_q partials (K-split 8 per matrix), z = mat*8 + ks
    {
        GS a;
        a.srcT[0] = st_dev;              a.srcT[1] = st_dev + DD * NR;
        a.wtsel[0] = 0;                  a.wtsel[1] = 1;
        k_gemmS2<8><<<dim3(12, 8, 16), 128>>>(a);
    }

    // Stage 2: folds stage-1 partials + bias; attention + residual + LN -> g_y, g_yT
    k_main<<<dim3(BB, 3), 512, E_BYTES>>>(X, H, KQ, bk, bq,
                                          kn_g, kn_b, norm_g, norm_b);

    // Stage 3: fc partials (K-split 8), src = g_yT
    {
        GS a;
        a.srcT[0] = yT_dev;              a.srcT[1] = yT_dev;
        a.wtsel[0] = 2;                  a.wtsel[1] = 2;
        k_gemmS2<8><<<dim3(12, 8, 8), 128>>>(a);
    }

    // Stage 4: out = p0..p7 + fc_b + y
    k_reduce2<<<192, 256>>>(fc_b, out);
}

// round 16
// speedup vs baseline: 1.2020x; 1.2020x over previous
#include <cuda_runtime.h>

#define DD 512
#define BB 128
#define EPSF 1e-5f
#define LOG2E_F 1.4426950408889634f
#define MATSZ (384 * 512)

// scratch (static device memory — no allocations)
__device__ float g_y [3 * BB * DD];
__device__ float g_wt[3 * DD * DD];      // k-major weights: [mat][k][m]
__device__ float g_part[16 * MATSZ];     // K-split partials

struct Ptr3 { const float* p[3]; };

__device__ __forceinline__ float ex2f(float x) {
    float y;
    asm("ex2.approx.ftz.f32 %0, %1;" : "=f"(y) : "f"(x));
    return y;
}

// ===================== transpose weights: g_wt[z][d][m] = W_z[m][d] =====================
__global__ void __launch_bounds__(256)
k_transpose(const float* __restrict__ W0, const float* __restrict__ W1,
            const float* __restrict__ W2)
{
    __shared__ float t[32][33];
    const float* W = (blockIdx.z == 0) ? W0 : (blockIdx.z == 1) ? W1 : W2;
    float* O = g_wt + (size_t)blockIdx.z * DD * DD;
    int x  = blockIdx.x * 32 + threadIdx.x;
    int y0 = blockIdx.y * 32;
    #pragma unroll
    for (int i = threadIdx.y; i < 32; i += 8)
        t[i][threadIdx.x] = W[(size_t)(y0 + i) * DD + x];
    __syncthreads();
    int xo  = blockIdx.y * 32 + threadIdx.x;
    int yo0 = blockIdx.x * 32;
    #pragma unroll
    for (int i = threadIdx.y; i < 32; i += 8)
        O[(size_t)(yo0 + i) * DD + xo] = t[threadIdx.x][i];
}

// ===================== GEMM vS (R14, proven): smem-only compute, K=64/block ==========
struct GS {
    Ptr3 src[2];
    int wtsel[2];
};

#define SST 68

template <int NKS>
__global__ void __launch_bounds__(128)
k_gemmS(GS a)
{
    __shared__ __align__(16) float sS[32][SST];   // [row][k]
    __shared__ __align__(16) float sW[64][SST];   // [k][col]

    int tid = threadIdx.x;
    int rt = blockIdx.x, ct = blockIdx.y, z = blockIdx.z;
    int mat = z / NKS, ks = z % NKS;
    int r0 = rt * 32, c0 = ct * 64, k0 = ks * 64;

    const float* src = a.src[mat].p[r0 >> 7] + (size_t)(r0 & 127) * DD;
    const float* wt  = g_wt + (size_t)a.wtsel[mat] * DD * DD + (size_t)k0 * DD + c0;

    #pragma unroll
    for (int it = 0; it < 4; it++) {
        int idx = it * 128 + tid;
        int row = idx >> 4, q = idx & 15;
        float4 v = *(const float4*)(src + (size_t)row * DD + k0 + q * 4);
        *(float4*)&sS[row][q * 4] = v;
    }
    #pragma unroll
    for (int it = 0; it < 8; it++) {
        int idx = it * 128 + tid;
        int k = idx >> 4, q = idx & 15;
        float4 w = *(const float4*)(wt + (size_t)k * DD + q * 4);
        *(float4*)&sW[k][q * 4] = w;
    }
    __syncthreads();

    int c4 = tid & 15;
    int rg = tid >> 4;

    float4 acc[4];
    #pragma unroll
    for (int r = 0; r < 4; r++) acc[r] = make_float4(0.f, 0.f, 0.f, 0.f);

    const float* s0 = &sS[4 * rg + 0][0];
    const float* s1 = &sS[4 * rg + 1][0];
    const float* s2 = &sS[4 * rg + 2][0];
    const float* s3 = &sS[4 * rg + 3][0];

    #pragma unroll 8
    for (int k = 0; k < 64; k++) {
        float4 w = *(const float4*)&sW[k][c4 * 4];
        float a0 = s0[k], a1 = s1[k], a2 = s2[k], a3 = s3[k];
        acc[0].x = fmaf(a0, w.x, acc[0].x);
        acc[0].y = fmaf(a0, w.y, acc[0].y);
        acc[0].z = fmaf(a0, w.z, acc[0].z);
        acc[0].w = fmaf(a0, w.w, acc[0].w);
        acc[1].x = fmaf(a1, w.x, acc[1].x);
        acc[1].y = fmaf(a1, w.y, acc[1].y);
        acc[1].z = fmaf(a1, w.z, acc[1].z);
        acc[1].w = fmaf(a1, w.w, acc[1].w);
        acc[2].x = fmaf(a2, w.x, acc[2].x);
        acc[2].y = fmaf(a2, w.y, acc[2].y);
        acc[2].z = fmaf(a2, w.z, acc[2].z);
        acc[2].w = fmaf(a2, w.w, acc[2].w);
        acc[3].x = fmaf(a3, w.x, acc[3].x);
        acc[3].y = fmaf(a3, w.y, acc[3].y);
        acc[3].z = fmaf(a3, w.z, acc[3].z);
        acc[3].w = fmaf(a3, w.w, acc[3].w);
    }

    float* outp = g_part + (size_t)z * MATSZ;
    #pragma unroll
    for (int r = 0; r < 4; r++) {
        int row = r0 + 4 * rg + r;
        *(float4*)(outp + (size_t)row * DD + c0 + c4 * 4) = acc[r];
    }
}

// ===================== fc final reduce: out = p0..p7 + fc_b + y (float4) =====================
__global__ void __launch_bounds__(256)
k_reduce2(const float* __restrict__ fcb, float* __restrict__ out)
{
    int idx = blockIdx.x * 256 + threadIdx.x;
    size_t i = (size_t)idx * 4;
    int col = (idx & 127) * 4;
    float4 s = *(const float4*)(g_part + i);
    #pragma unroll
    for (int q = 1; q < 8; q++) {
        float4 v = *(const float4*)(g_part + (size_t)q * MATSZ + i);
        s.x += v.x; s.y += v.y; s.z += v.z; s.w += v.w;
    }
    float4 bb = *(const float4*)(fcb + col);
    float4 yy = *(const float4*)(g_y + i);
    s.x += bb.x + yy.x;
    s.y += bb.y + yy.y;
    s.z += bb.z + yy.z;
    s.w += bb.w + yy.w;
    *(float4*)(out + i) = s;
}

// ---- block reductions over 512 threads (16 warps) ----
__device__ __forceinline__ float blockReduceSum(float v, float* red) {
    int tid = threadIdx.x, lane = tid & 31, wid = tid >> 5;
    #pragma unroll
    for (int o = 16; o > 0; o >>= 1) v += __shfl_down_sync(0xffffffffu, v, o);
    if (lane == 0) red[wid] = v;
    __syncthreads();
    if (wid == 0) {
        float x = (lane < 16) ? red[lane] : 0.0f;
        #pragma unroll
        for (int o = 8; o > 0; o >>= 1) x += __shfl_down_sync(0xffffffffu, x, o);
        if (lane == 0) red[0] = x;
    }
    __syncthreads();
    float r = red[0];
    __syncthreads();
    return r;
}

__device__ __forceinline__ float blockReduceMax(float v, float* red) {
    int tid = threadIdx.x, lane = tid & 31, wid = tid >> 5;
    #pragma unroll
    for (int o = 16; o > 0; o >>= 1) v = fmaxf(v, __shfl_down_sync(0xffffffffu, v, o));
    if (lane == 0) red[wid] = v;
    __syncthreads();
    if (wid == 0) {
        float x = (lane < 16) ? red[lane] : -3.4e38f;
        #pragma unroll
        for (int o = 8; o > 0; o >>= 1) x = fmaxf(x, __shfl_down_sync(0xffffffffu, x, o));
        if (lane == 0) red[0] = x;
    }
    __syncthreads();
    float r = red[0];
    __syncthreads();
    return r;
}

__device__ __forceinline__ float blockReduceMin(float v, float* red) {
    int tid = threadIdx.x, lane = tid & 31, wid = tid >> 5;
    #pragma unroll
    for (int o = 16; o > 0; o >>= 1) v = fminf(v, __shfl_down_sync(0xffffffffu, v, o));
    if (lane == 0) red[wid] = v;
    __syncthreads();
    if (wid == 0) {
        float x = (lane < 16) ? red[lane] : 3.4e38f;
        #pragma unroll
        for (int o = 8; o > 0; o >>= 1) x = fminf(x, __shfl_down_sync(0xffffffffu, x, o));
        if (lane == 0) red[0] = x;
    }
    __syncthreads();
    float r = red[0];
    __syncthreads();
    return r;
}

// ---- main fused kernel: one block per (batch, channel) ----
// E stays in registers (e[32] per thread); only scalar Z-partials + one final per-warp
// 32x33 buffer touch shared memory. Folds stage-1 K-split-8 partials + bias.
__global__ void __launch_bounds__(512)
k_main(Ptr3 x, Ptr3 h, Ptr3 kq,
       const float* __restrict__ bk, const float* __restrict__ bq,
       const float* __restrict__ kn_g, const float* __restrict__ kn_b,
       const float* __restrict__ norm_g, const float* __restrict__ norm_b)
{
    extern __shared__ float B[];              // [16][32][33] per-warp reduce buffers
    __shared__ float s_s[DD], s_u2[DD], s_v[DD];
    __shared__ float Zpart[16][33];
    __shared__ float coefT[32];
    __shared__ float red[32];

    int b = blockIdx.x, c = blockIdx.y, tid = threadIdx.x;
    int row = c * BB + b;
    size_t ri = (size_t)row * DD + tid;

    float wk = bk[tid];
    float wq = bq[tid];
    #pragma unroll
    for (int q = 0; q < 8; q++) wk += g_part[(size_t)q * MATSZ + ri];
    #pragma unroll
    for (int q = 8; q < 16; q++) wq += g_part[(size_t)q * MATSZ + ri];

    float kv = h.p[c][(size_t)b * DD + tid];
    float qv = kq.p[c][(size_t)b * DD + tid];
    float vv = x.p[c][(size_t)b * DD + tid];

    const float inv_d = 1.0f / (float)DD;
    float mu_wk  = blockReduceSum(wk, red) * inv_d;
    float dk     = wk - mu_wk;
    float var_wk = blockReduceSum(dk * dk, red) * inv_d;
    float mu_wq  = blockReduceSum(wq, red) * inv_d;
    float dq     = wq - mu_wq;
    float var_wq = blockReduceSum(dq * dq, red) * inv_d;

    float gg = kn_g[tid];
    float cb = kn_b[tid];

    float si = kv * rsqrtf(kv * kv * var_wk + EPSF);
    float ti = qv * rsqrtf(qv * qv * var_wq + EPSF);
    float Ai = dk * gg;
    float Bi = dq * gg;

    float P    = blockReduceSum(Ai * ti, red);
    float Qs   = blockReduceSum(Ai, red);
    float smax = blockReduceMax(si, red);
    float smin = blockReduceMin(si, red);

    float u2 = (P * Bi + Qs * cb) * LOG2E_F;
    s_s[tid]  = si;
    s_u2[tid] = u2;
    s_v[tid]  = vv;
    __syncthreads();

    int g = tid >> 5;          // warp: i-chunk [32g, 32g+32)
    int j = tid & 31;          // lane: column within j-tile
    const float* sbase = s_s + g * 32;

    float acc[32];
    #pragma unroll
    for (int i = 0; i < 32; i++) acc[i] = 0.0f;

    #pragma unroll 1
    for (int jt = 0; jt < DD; jt += 32) {
        float u2j = s_u2[jt + j];
        float m2j = fmaxf(u2j * smax, u2j * smin);
        float e[32];
        float Zl = 0.0f;
        #pragma unroll
        for (int i4 = 0; i4 < 32; i4 += 4) {
            float4 s4 = *(const float4*)(sbase + i4);    // broadcast LDS
            e[i4 + 0] = ex2f(fmaf(s4.x, u2j, -m2j));
            e[i4 + 1] = ex2f(fmaf(s4.y, u2j, -m2j));
            e[i4 + 2] = ex2f(fmaf(s4.z, u2j, -m2j));
            e[i4 + 3] = ex2f(fmaf(s4.w, u2j, -m2j));
            Zl += (e[i4 + 0] + e[i4 + 1]) + (e[i4 + 2] + e[i4 + 3]);
        }
        Zpart[g][j] = Zl;
        __syncthreads();

        if (tid < 32) {
            float zt = 0.0f;
            #pragma unroll
            for (int w = 0; w < 16; w++) zt += Zpart[w][tid];
            coefT[tid] = s_v[jt + tid] / zt;
        }
        __syncthreads();

        float cf = coefT[j];
        #pragma unroll
        for (int i = 0; i < 32; i++)
            acc[i] = fmaf(cf, e[i], acc[i]);
    }

    // once-per-block cross-lane reduction via per-warp 32x33 smem buffers
    float* bufg = B + (size_t)g * (32 * 33);
    #pragma unroll
    for (int i = 0; i < 32; i++)
        bufg[i * 33 + j] = acc[i];
    __syncwarp();
    float mha = 0.0f;
    #pragma unroll
    for (int jj = 0; jj < 32; jj++)
        mha += bufg[j * 33 + jj];
    // mha corresponds to feature i_global = 32g + j = tid

    float y     = mha + vv;
    float mu_y  = blockReduceSum(y, red) * inv_d;
    float dy    = y - mu_y;
    float var_y = blockReduceSum(dy * dy, red) * inv_d;
    float yn    = dy * rsqrtf(var_y + EPSF) * norm_g[tid] + norm_b[tid];

    g_y[(size_t)row * DD + tid] = yn;
}

extern "C" void kernel_launch(void* const* d_in, const int* in_sizes, int n_in,
                              void* d_out, int out_size)
{
    (void)in_sizes; (void)n_in; (void)out_size;
    const float* r    = (const float*)d_in[0];
    const float* g    = (const float*)d_in[1];
    const float* b    = (const float*)d_in[2];
    const float* h_r  = (const float*)d_in[3];
    const float* h_g  = (const float*)d_in[4];
    const float* h_b  = (const float*)d_in[5];
    const float* k_r  = (const float*)d_in[6];
    const float* k_g  = (const float*)d_in[7];
    const float* k_b  = (const float*)d_in[8];
    const float* Wk   = (const float*)d_in[9];
    const float* bk   = (const float*)d_in[10];
    const float* Wq   = (const float*)d_in[11];
    const float* bq   = (const float*)d_in[12];
    const float* kn_g = (const float*)d_in[13];
    const float* kn_b = (const float*)d_in[14];
    const float* norm_g = (const float*)d_in[15];
    const float* norm_b = (const float*)d_in[16];
    const float* fc_w = (const float*)d_in[17];
    const float* fc_b = (const float*)d_in[18];
    float* out = (float*)d_out;

    Ptr3 X  = {{ r,   g,   b   }};
    Ptr3 H  = {{ h_r, h_g, h_b }};
    Ptr3 KQ = {{ k_r, k_g, k_b }};

    const size_t B_BYTES = 16 * 32 * 33 * sizeof(float);   // 67.6 KB

    static float* y_dev  = nullptr;
    if (y_dev == nullptr) {
        void* p = nullptr;
        cudaGetSymbolAddress(&p, g_y);  y_dev = (float*)p;
        cudaFuncSetAttribute(k_main, cudaFuncAttributeMaxDynamicSharedMemorySize,
                             (int)B_BYTES);
    }

    // Stage 0: transpose weights -> g_wt (k-major)
    k_transpose<<<dim3(16, 16, 3), dim3(32, 8)>>>(Wk, Wq, fc_w);

    // Stage 1: w_k / w_q partials (K-split 8 per matrix), z = mat*8 + ks
    {
        GS a;
        a.src[0] = H;  a.src[1] = KQ;
        a.wtsel[0] = 0; a.wtsel[1] = 1;
        k_gemmS<8><<<dim3(12, 8, 16), 128>>>(a);
    }

    // Stage 2: folds stage-1 partials + bias; attention + residual + LN -> g_y
    k_main<<<dim3(BB, 3), 512, B_BYTES>>>(X, H, KQ, bk, bq,
                                          kn_g, kn_b, norm_g, norm_b);

    // Stage 3: fc partials (K-split 8), src = g_y
    {
        Ptr3 Y = {{ y_dev, y_dev + BB * DD, y_dev + 2 * BB * DD }};
        GS a;
        a.src[0] = Y;  a.src[1] = Y;
        a.wtsel[0] = 2; a.wtsel[1] = 2;
        k_gemmS<8><<<dim3(12, 8, 8), 128>>>(a);
    }

    // Stage 4: out = p0..p7 + fc_b + y
    k_reduce2<<<192, 256>>>(fc_b, out);
}

// round 17
// speedup vs baseline: 1.2056x; 1.0030x over previous
#include <cuda_runtime.h>

#define DD 512
#define BB 128
#define EPSF 1e-5f
#define LOG2E_F 1.4426950408889634f
#define MATSZ (384 * 512)

// scratch (static device memory — no allocations)
__device__ float g_y [3 * BB * DD];
__device__ float g_wt[3 * DD * DD];      // k-major weights: [mat][k][m]
__device__ float g_part[8 * MATSZ];      // K-split partials

struct Ptr3 { const float* p[3]; };

__device__ __forceinline__ float ex2f(float x) {
    float y;
    asm("ex2.approx.ftz.f32 %0, %1;" : "=f"(y) : "f"(x));
    return y;
}

// ===================== transpose weights: g_wt[z][d][m] = W_z[m][d] =====================
__global__ void __launch_bounds__(256)
k_transpose(const float* __restrict__ W0, const float* __restrict__ W1,
            const float* __restrict__ W2)
{
    __shared__ float t[32][33];
    const float* W = (blockIdx.z == 0) ? W0 : (blockIdx.z == 1) ? W1 : W2;
    float* O = g_wt + (size_t)blockIdx.z * DD * DD;
    int x  = blockIdx.x * 32 + threadIdx.x;
    int y0 = blockIdx.y * 32;
    #pragma unroll
    for (int i = threadIdx.y; i < 32; i += 8)
        t[i][threadIdx.x] = W[(size_t)(y0 + i) * DD + x];
    __syncthreads();
    int xo  = blockIdx.y * 32 + threadIdx.x;
    int yo0 = blockIdx.x * 32;
    #pragma unroll
    for (int i = threadIdx.y; i < 32; i += 8)
        O[(size_t)(yo0 + i) * DD + xo] = t[threadIdx.x][i];
}

// ===================== GEMM vD: K=128/block, double-buffered smem =====================
// g_part[z][row][col] = sum_{k in slice of 128} src[row][k] * Wt[k][col]
// block 128 thr; tile 32r x 64c; two 64-k chunks, register-staged pipeline.
struct GS {
    Ptr3 src[2];
    int wtsel[2];
};

#define SST 68
#define GD_SMEM ((2 * 32 * SST + 2 * 64 * SST) * 4)   // 52224 B

template <int NKS>
__global__ void __launch_bounds__(128)
k_gemmD(GS a)
{
    extern __shared__ float dsm[];
    float (*sS)[SST] = (float (*)[SST])dsm;                       // [2*32][SST]
    float (*sW)[SST] = (float (*)[SST])(dsm + 2 * 32 * SST);      // [2*64][SST]

    int tid = threadIdx.x;
    int rt = blockIdx.x, ct = blockIdx.y, z = blockIdx.z;
    int mat = z / NKS, ks = z % NKS;
    int r0 = rt * 32, c0 = ct * 64, k0 = ks * 128;

    const float* src = a.src[mat].p[r0 >> 7] + (size_t)(r0 & 127) * DD;
    const float* wt  = g_wt + (size_t)a.wtsel[mat] * DD * DD + (size_t)k0 * DD + c0;

    int srow = tid >> 4, sq = tid & 15;       // src staging: 8 row-steps of 4
    int wk_  = tid >> 4, wq_ = tid & 15;      // wt staging

    float4 rs[4], rw[8];

    // ---- load chunk 0 into registers ----
    #pragma unroll
    for (int it = 0; it < 4; it++)
        rs[it] = *(const float4*)(src + (size_t)(it * 8 + srow) * DD + k0 + sq * 4);
    #pragma unroll
    for (int it = 0; it < 8; it++)
        rw[it] = *(const float4*)(wt + (size_t)(it * 8 + wk_) * DD + wq_ * 4);

    // ---- store chunk 0 to buffer 0 ----
    #pragma unroll
    for (int it = 0; it < 4; it++)
        *(float4*)&sS[it * 8 + srow][sq * 4] = rs[it];
    #pragma unroll
    for (int it = 0; it < 8; it++)
        *(float4*)&sW[it * 8 + wk_][wq_ * 4] = rw[it];
    __syncthreads();

    // ---- issue chunk-1 loads (fly under chunk-0 compute) ----
    #pragma unroll
    for (int it = 0; it < 4; it++)
        rs[it] = *(const float4*)(src + (size_t)(it * 8 + srow) * DD + k0 + 64 + sq * 4);
    #pragma unroll
    for (int it = 0; it < 8; it++)
        rw[it] = *(const float4*)(wt + (size_t)(64 + it * 8 + wk_) * DD + wq_ * 4);

    int c4 = tid & 15;
    int rg = tid >> 4;

    float4 acc[4];
    #pragma unroll
    for (int r = 0; r < 4; r++) acc[r] = make_float4(0.f, 0.f, 0.f, 0.f);

    const float* s0 = &sS[4 * rg + 0][0];
    const float* s1 = &sS[4 * rg + 1][0];
    const float* s2 = &sS[4 * rg + 2][0];
    const float* s3 = &sS[4 * rg + 3][0];

    // ---- compute chunk 0 ----
    #pragma unroll 8
    for (int k = 0; k < 64; k++) {
        float4 w = *(const float4*)&sW[k][c4 * 4];
        float a0 = s0[k], a1 = s1[k], a2 = s2[k], a3 = s3[k];
        acc[0].x = fmaf(a0, w.x, acc[0].x);
        acc[0].y = fmaf(a0, w.y, acc[0].y);
        acc[0].z = fmaf(a0, w.z, acc[0].z);
        acc[0].w = fmaf(a0, w.w, acc[0].w);
        acc[1].x = fmaf(a1, w.x, acc[1].x);
        acc[1].y = fmaf(a1, w.y, acc[1].y);
        acc[1].z = fmaf(a1, w.z, acc[1].z);
        acc[1].w = fmaf(a1, w.w, acc[1].w);
        acc[2].x = fmaf(a2, w.x, acc[2].x);
        acc[2].y = fmaf(a2, w.y, acc[2].y);
        acc[2].z = fmaf(a2, w.z, acc[2].z);
        acc[2].w = fmaf(a2, w.w, acc[2].w);
        acc[3].x = fmaf(a3, w.x, acc[3].x);
        acc[3].y = fmaf(a3, w.y, acc[3].y);
        acc[3].z = fmaf(a3, w.z, acc[3].z);
        acc[3].w = fmaf(a3, w.w, acc[3].w);
    }

    // ---- store chunk 1 to buffer 1 (waits on LDGs) ----
    #pragma unroll
    for (int it = 0; it < 4; it++)
        *(float4*)&sS[32 + it * 8 + srow][sq * 4] = rs[it];
    #pragma unroll
    for (int it = 0; it < 8; it++)
        *(float4*)&sW[64 + it * 8 + wk_][wq_ * 4] = rw[it];
    __syncthreads();

    const float* t0 = &sS[32 + 4 * rg + 0][0];
    const float* t1 = &sS[32 + 4 * rg + 1][0];
    const float* t2 = &sS[32 + 4 * rg + 2][0];
    const float* t3 = &sS[32 + 4 * rg + 3][0];

    // ---- compute chunk 1 ----
    #pragma unroll 8
    for (int k = 0; k < 64; k++) {
        float4 w = *(const float4*)&sW[64 + k][c4 * 4];
        float a0 = t0[k], a1 = t1[k], a2 = t2[k], a3 = t3[k];
        acc[0].x = fmaf(a0, w.x, acc[0].x);
        acc[0].y = fmaf(a0, w.y, acc[0].y);
        acc[0].z = fmaf(a0, w.z, acc[0].z);
        acc[0].w = fmaf(a0, w.w, acc[0].w);
        acc[1].x = fmaf(a1, w.x, acc[1].x);
        acc[1].y = fmaf(a1, w.y, acc[1].y);
        acc[1].z = fmaf(a1, w.z, acc[1].z);
        acc[1].w = fmaf(a1, w.w, acc[1].w);
        acc[2].x = fmaf(a2, w.x, acc[2].x);
        acc[2].y = fmaf(a2, w.y, acc[2].y);
        acc[2].z = fmaf(a2, w.z, acc[2].z);
        acc[2].w = fmaf(a2, w.w, acc[2].w);
        acc[3].x = fmaf(a3, w.x, acc[3].x);
        acc[3].y = fmaf(a3, w.y, acc[3].y);
        acc[3].z = fmaf(a3, w.z, acc[3].z);
        acc[3].w = fmaf(a3, w.w, acc[3].w);
    }

    float* outp = g_part + (size_t)z * MATSZ;
    #pragma unroll
    for (int r = 0; r < 4; r++) {
        int row = r0 + 4 * rg + r;
        *(float4*)(outp + (size_t)row * DD + c0 + c4 * 4) = acc[r];
    }
}

// ===================== fc final reduce: out = p0..p3 + fc_b + y (float4) =====================
__global__ void __launch_bounds__(256)
k_reduce2(const float* __restrict__ fcb, float* __restrict__ out)
{
    int idx = blockIdx.x * 256 + threadIdx.x;
    size_t i = (size_t)idx * 4;
    int col = (idx & 127) * 4;
    float4 s = *(const float4*)(g_part + i);
    #pragma unroll
    for (int q = 1; q < 4; q++) {
        float4 v = *(const float4*)(g_part + (size_t)q * MATSZ + i);
        s.x += v.x; s.y += v.y; s.z += v.z; s.w += v.w;
    }
    float4 bb = *(const float4*)(fcb + col);
    float4 yy = *(const float4*)(g_y + i);
    s.x += bb.x + yy.x;
    s.y += bb.y + yy.y;
    s.z += bb.z + yy.z;
    s.w += bb.w + yy.w;
    *(float4*)(out + i) = s;
}

// ---- block reductions over 512 threads (16 warps) ----
__device__ __forceinline__ float blockReduceSum(float v, float* red) {
    int tid = threadIdx.x, lane = tid & 31, wid = tid >> 5;
    #pragma unroll
    for (int o = 16; o > 0; o >>= 1) v += __shfl_down_sync(0xffffffffu, v, o);
    if (lane == 0) red[wid] = v;
    __syncthreads();
    if (wid == 0) {
        float x = (lane < 16) ? red[lane] : 0.0f;
        #pragma unroll
        for (int o = 8; o > 0; o >>= 1) x += __shfl_down_sync(0xffffffffu, x, o);
        if (lane == 0) red[0] = x;
    }
    __syncthreads();
    float r = red[0];
    __syncthreads();
    return r;
}

__device__ __forceinline__ float blockReduceMax(float v, float* red) {
    int tid = threadIdx.x, lane = tid & 31, wid = tid >> 5;
    #pragma unroll
    for (int o = 16; o > 0; o >>= 1) v = fmaxf(v, __shfl_down_sync(0xffffffffu, v, o));
    if (lane == 0) red[wid] = v;
    __syncthreads();
    if (wid == 0) {
        float x = (lane < 16) ? red[lane] : -3.4e38f;
        #pragma unroll
        for (int o = 8; o > 0; o >>= 1) x = fmaxf(x, __shfl_down_sync(0xffffffffu, x, o));
        if (lane == 0) red[0] = x;
    }
    __syncthreads();
    float r = red[0];
    __syncthreads();
    return r;
}

__device__ __forceinline__ float blockReduceMin(float v, float* red) {
    int tid = threadIdx.x, lane = tid & 31, wid = tid >> 5;
    #pragma unroll
    for (int o = 16; o > 0; o >>= 1) v = fminf(v, __shfl_down_sync(0xffffffffu, v, o));
    if (lane == 0) red[wid] = v;
    __syncthreads();
    if (wid == 0) {
        float x = (lane < 16) ? red[lane] : 3.4e38f;
        #pragma unroll
        for (int o = 8; o > 0; o >>= 1) x = fminf(x, __shfl_down_sync(0xffffffffu, x, o));
        if (lane == 0) red[0] = x;
    }
    __syncthreads();
    float r = red[0];
    __syncthreads();
    return r;
}

// ---- main fused kernel: one block per (batch, channel) ----
// E stays in registers; folds stage-1 K-split-4 partials + bias.
__global__ void __launch_bounds__(512)
k_main(Ptr3 x, Ptr3 h, Ptr3 kq,
       const float* __restrict__ bk, const float* __restrict__ bq,
       const float* __restrict__ kn_g, const float* __restrict__ kn_b,
       const float* __restrict__ norm_g, const float* __restrict__ norm_b)
{
    extern __shared__ float B[];              // [16][32][33] per-warp reduce buffers
    __shared__ float s_s[DD], s_u2[DD], s_v[DD];
    __shared__ float Zpart[16][33];
    __shared__ float coefT[32];
    __shared__ float red[32];

    int b = blockIdx.x, c = blockIdx.y, tid = threadIdx.x;
    int row = c * BB + b;
    size_t ri = (size_t)row * DD + tid;

    float wk = bk[tid];
    float wq = bq[tid];
    #pragma unroll
    for (int q = 0; q < 4; q++) wk += g_part[(size_t)q * MATSZ + ri];
    #pragma unroll
    for (int q = 4; q < 8; q++) wq += g_part[(size_t)q * MATSZ + ri];

    float kv = h.p[c][(size_t)b * DD + tid];
    float qv = kq.p[c][(size_t)b * DD + tid];
    float vv = x.p[c][(size_t)b * DD + tid];

    const float inv_d = 1.0f / (float)DD;
    float mu_wk  = blockReduceSum(wk, red) * inv_d;
    float dk     = wk - mu_wk;
    float var_wk = blockReduceSum(dk * dk, red) * inv_d;
    float mu_wq  = blockReduceSum(wq, red) * inv_d;
    float dq     = wq - mu_wq;
    float var_wq = blockReduceSum(dq * dq, red) * inv_d;

    float gg = kn_g[tid];
    float cb = kn_b[tid];

    float si = kv * rsqrtf(kv * kv * var_wk + EPSF);
    float ti = qv * rsqrtf(qv * qv * var_wq + EPSF);
    float Ai = dk * gg;
    float Bi = dq * gg;

    float P    = blockReduceSum(Ai * ti, red);
    float Qs   = blockReduceSum(Ai, red);
    float smax = blockReduceMax(si, red);
    float smin = blockReduceMin(si, red);

    float u2 = (P * Bi + Qs * cb) * LOG2E_F;
    s_s[tid]  = si;
    s_u2[tid] = u2;
    s_v[tid]  = vv;
    __syncthreads();

    int g = tid >> 5;          // warp: i-chunk [32g, 32g+32)
    int j = tid & 31;          // lane: column within j-tile
    const float* sbase = s_s + g * 32;

    float acc[32];
    #pragma unroll
    for (int i = 0; i < 32; i++) acc[i] = 0.0f;

    #pragma unroll 1
    for (int jt = 0; jt < DD; jt += 32) {
        float u2j = s_u2[jt + j];
        float m2j = fmaxf(u2j * smax, u2j * smin);
        float e[32];
        float Zl = 0.0f;
        #pragma unroll
        for (int i4 = 0; i4 < 32; i4 += 4) {
            float4 s4 = *(const float4*)(sbase + i4);    // broadcast LDS
            e[i4 + 0] = ex2f(fmaf(s4.x, u2j, -m2j));
            e[i4 + 1] = ex2f(fmaf(s4.y, u2j, -m2j));
            e[i4 + 2] = ex2f(fmaf(s4.z, u2j, -m2j));
            e[i4 + 3] = ex2f(fmaf(s4.w, u2j, -m2j));
            Zl += (e[i4 + 0] + e[i4 + 1]) + (e[i4 + 2] + e[i4 + 3]);
        }
        Zpart[g][j] = Zl;
        __syncthreads();

        if (tid < 32) {
            float zt = 0.0f;
            #pragma unroll
            for (int w = 0; w < 16; w++) zt += Zpart[w][tid];
            coefT[tid] = s_v[jt + tid] / zt;
        }
        __syncthreads();

        float cf = coefT[j];
        #pragma unroll
        for (int i = 0; i < 32; i++)
            acc[i] = fmaf(cf, e[i], acc[i]);
    }

    // once-per-block cross-lane reduction via per-warp 32x33 smem buffers
    float* bufg = B + (size_t)g * (32 * 33);
    #pragma unroll
    for (int i = 0; i < 32; i++)
        bufg[i * 33 + j] = acc[i];
    __syncwarp();
    float mha = 0.0f;
    #pragma unroll
    for (int jj = 0; jj < 32; jj++)
        mha += bufg[j * 33 + jj];

    float y     = mha + vv;
    float mu_y  = blockReduceSum(y, red) * inv_d;
    float dy    = y - mu_y;
    float var_y = blockReduceSum(dy * dy, red) * inv_d;
    float yn    = dy * rsqrtf(var_y + EPSF) * norm_g[tid] + norm_b[tid];

    g_y[(size_t)row * DD + tid] = yn;
}

extern "C" void kernel_launch(void* const* d_in, const int* in_sizes, int n_in,
                              void* d_out, int out_size)
{
    (void)in_sizes; (void)n_in; (void)out_size;
    const float* r    = (const float*)d_in[0];
    const float* g    = (const float*)d_in[1];
    const float* b    = (const float*)d_in[2];
    const float* h_r  = (const float*)d_in[3];
    const float* h_g  = (const float*)d_in[4];
    const float* h_b  = (const float*)d_in[5];
    const float* k_r  = (const float*)d_in[6];
    const float* k_g  = (const float*)d_in[7];
    const float* k_b  = (const float*)d_in[8];
    const float* Wk   = (const float*)d_in[9];
    const float* bk   = (const float*)d_in[10];
    const float* Wq   = (const float*)d_in[11];
    const float* bq   = (const float*)d_in[12];
    const float* kn_g = (const float*)d_in[13];
    const float* kn_b = (const float*)d_in[14];
    const float* norm_g = (const float*)d_in[15];
    const float* norm_b = (const float*)d_in[16];
    const float* fc_w = (const float*)d_in[17];
    const float* fc_b = (const float*)d_in[18];
    float* out = (float*)d_out;

    Ptr3 X  = {{ r,   g,   b   }};
    Ptr3 H  = {{ h_r, h_g, h_b }};
    Ptr3 KQ = {{ k_r, k_g, k_b }};

    const size_t B_BYTES = 16 * 32 * 33 * sizeof(float);   // 67.6 KB

    static float* y_dev  = nullptr;
    if (y_dev == nullptr) {
        void* p = nullptr;
        cudaGetSymbolAddress(&p, g_y);  y_dev = (float*)p;
        cudaFuncSetAttribute(k_main, cudaFuncAttributeMaxDynamicSharedMemorySize,
                             (int)B_BYTES);
        cudaFuncSetAttribute(k_gemmD<4>, cudaFuncAttributeMaxDynamicSharedMemorySize,
                             GD_SMEM);
    }

    // Stage 0: transpose weights -> g_wt (k-major)
    k_transpose<<<dim3(16, 16, 3), dim3(32, 8)>>>(Wk, Wq, fc_w);

    // Stage 1: w_k / w_q partials (K-split 4 per matrix, K=128/block), z = mat*4 + ks
    {
        GS a;
        a.src[0] = H;  a.src[1] = KQ;
        a.wtsel[0] = 0; a.wtsel[1] = 1;
        k_gemmD<4><<<dim3(12, 8, 8), 128, GD_SMEM>>>(a);
    }

    // Stage 2: folds stage-1 partials + bias; attention + residual + LN -> g_y
    k_main<<<dim3(BB, 3), 512, B_BYTES>>>(X, H, KQ, bk, bq,
                                          kn_g, kn_b, norm_g, norm_b);

    // Stage 3: fc partials (K-split 4, K=128/block), src = g_y
    {
        Ptr3 Y = {{ y_dev, y_dev + BB * DD, y_dev + 2 * BB * DD }};
        GS a;
        a.src[0] = Y;  a.src[1] = Y;
        a.wtsel[0] = 2; a.wtsel[1] = 2;
        k_gemmD<4><<<dim3(12, 8, 4), 128, GD_SMEM>>>(a);
    }

    // Stage 4: out = p0..p3 + fc_b + y
    k_reduce2<<<192, 256>>>(fc_b, out);
}